// round 16
// baseline (speedup 1.0000x reference)
#include <cuda_runtime.h>
#include <cuda_bf16.h>
#include <cstdint>

// Dims (fixed): B=8, N=4096 -> M=32768; D=1024; E=512; C=4096
#define M_ROWS 32768
#define D_DIM  1024
#define E_DIM  512
#define C_DIM  4096

#define X_ELEMS  (M_ROWS * D_DIM)   // 33554432
#define RP_ELEMS (D_DIM * E_DIM)    // 524288
#define CB_ELEMS (C_DIM * E_DIM)    // 2097152

// Scratch (device globals: allocation-free per harness rules).
__device__ __align__(256) __nv_bfloat16  g_xs[(size_t)3 * M_ROWS * D_DIM];  // 192 MB x splits [M][D]
__device__ __align__(256) __nv_bfloat16  g_rps[(size_t)3 * E_DIM * D_DIM]; //   3 MB RP^T splits [N][K]
__device__ __align__(256) __nv_bfloat16  g_ps[(size_t)3 * M_ROWS * E_DIM]; //  96 MB proj splits [M][E]
__device__ __align__(256) __nv_bfloat16  g_cbs[(size_t)3 * C_DIM * E_DIM]; //  12 MB normalized-cb splits

// Arch-specific gate: tcgen05 exists only on sm_103a-style targets.
#if defined(__CUDA_ARCH_FEAT_SM103_ALL)
#define HAS_TCGEN05 1
#elif defined(__CUDA_ARCH_SPECIFIC__)
#if __CUDA_ARCH_SPECIFIC__ == 1030
#define HAS_TCGEN05 1
#endif
#endif

// fp32 -> 3 exact-residual bf16 splits
__device__ __forceinline__ void split3(float v, __nv_bfloat16& b1, __nv_bfloat16& b2, __nv_bfloat16& b3) {
    b1 = __float2bfloat16(v);
    float r = v - __bfloat162float(b1);
    b2 = __float2bfloat16(r);
    b3 = __float2bfloat16(r - __bfloat162float(b2));
}

// ========== prep kernels (unchanged, verified) ==========
__global__ void split_x(const float* __restrict__ x) {
    const size_t i = ((size_t)blockIdx.x * blockDim.x + threadIdx.x) * 4;
    float4 v = *(const float4*)(x + i);
    float a[4] = { v.x, v.y, v.z, v.w };
    __nv_bfloat16 h[3][4];
    #pragma unroll
    for (int j = 0; j < 4; j++) split3(a[j], h[0][j], h[1][j], h[2][j]);
    #pragma unroll
    for (int s = 0; s < 3; s++)
        *(uint2*)(g_xs + (size_t)s * M_ROWS * D_DIM + i) = *(uint2*)h[s];
}

__global__ void split_rpt(const float* __restrict__ rp) {
    __shared__ float t[32][33];
    const int tx = threadIdx.x, ty = threadIdx.y;       // 32 x 8
    const int n0 = blockIdx.x * 32, k0 = blockIdx.y * 32;
    #pragma unroll
    for (int i = 0; i < 4; i++)
        t[ty + 8 * i][tx] = rp[(size_t)(k0 + ty + 8 * i) * E_DIM + n0 + tx];
    __syncthreads();
    #pragma unroll
    for (int i = 0; i < 4; i++) {
        float v = t[tx][ty + 8 * i];
        __nv_bfloat16 b1, b2, b3;
        split3(v, b1, b2, b3);
        const size_t o = (size_t)(n0 + ty + 8 * i) * D_DIM + k0 + tx;
        g_rps[o] = b1;
        g_rps[(size_t)E_DIM * D_DIM + o] = b2;
        g_rps[2 * (size_t)E_DIM * D_DIM + o] = b3;
    }
}

__global__ void split_cbn(const float* __restrict__ cb) {
    __shared__ float red[4];
    const int c = blockIdx.x, t = threadIdx.x;   // 128 threads
    const float* v = cb + (size_t)c * E_DIM;
    float4 x = *(const float4*)(v + t * 4);
    float ss = x.x * x.x + x.y * x.y + x.z * x.z + x.w * x.w;
    #pragma unroll
    for (int o = 16; o > 0; o >>= 1) ss += __shfl_xor_sync(0xffffffffu, ss, o);
    if ((t & 31) == 0) red[t >> 5] = ss;
    __syncthreads();
    const float inv = 1.f / fmaxf(sqrtf(red[0] + red[1] + red[2] + red[3]), 1e-12f);
    float a[4] = { x.x * inv, x.y * inv, x.z * inv, x.w * inv };
    __nv_bfloat16 h[3][4];
    #pragma unroll
    for (int j = 0; j < 4; j++) split3(a[j], h[0][j], h[1][j], h[2][j]);
    const size_t base = (size_t)c * E_DIM + t * 4;
    #pragma unroll
    for (int s = 0; s < 3; s++)
        *(uint2*)(g_cbs + (size_t)s * C_DIM * E_DIM + base) = *(uint2*)h[s];
}

// ================= tcgen05 / async PTX helpers ================
__device__ __forceinline__ uint32_t elect_one_pred() {
    uint32_t pred;
    asm volatile("{\n\t.reg .pred p;\n\telect.sync _|p, 0xFFFFFFFF;\n\t"
                 "selp.b32 %0, 1, 0, p;\n\t}" : "=r"(pred));
    return pred;
}
__device__ __forceinline__ uint32_t smem_to_u32(const void* p) {
    uint32_t a;
    asm("{ .reg .u64 t; cvta.to.shared.u64 t, %1; cvt.u32.u64 %0, t; }" : "=r"(a) : "l"(p));
    return a;
}
__device__ __forceinline__ void cp16(uint32_t dst, const void* src) {
    asm volatile("cp.async.cg.shared.global [%0], [%1], 16;" :: "r"(dst), "l"(src));
}
#define CP_COMMIT()  asm volatile("cp.async.commit_group;" ::: "memory")
#define CP_WAIT_1()  asm volatile("cp.async.wait_group 1;" ::: "memory")
#define CP_WAIT_0()  asm volatile("cp.async.wait_group 0;" ::: "memory")

#define SMEM_SWIZZLE_128B(off) ((off) ^ (((off) >> 3) & 0x70))
static constexpr unsigned long long SMEM_DESC_BASE_SW128 =
    (2ull << 61) | (1ull << 46) | (64ull << 32) | (1ull << 16);
#define MAKE_SMEM_DESC(a) (SMEM_DESC_BASE_SW128 | ((unsigned long long)((a) >> 4) & 0x3FFF))

#define MBARRIER_INIT(mb, n) \
    asm volatile("mbarrier.init.shared.b64 [%0], %1;" :: "r"((uint32_t)(mb)), "r"((uint32_t)(n)) : "memory")
#define MBARRIER_WAIT_PARITY(mb, par) do {                                        \
    uint32_t _m = (uint32_t)(mb), _p = (uint32_t)(par), _d;                        \
    asm volatile("{\n\t.reg .pred p;\n\t"                                          \
        "mbarrier.try_wait.parity.acquire.cta.shared::cta.b64 p, [%1], %2;\n\t"    \
        "selp.b32 %0, 1, 0, p;\n\t}" : "=r"(_d) : "r"(_m), "r"(_p) : "memory");    \
    if (!_d) {                                                                     \
        asm volatile("{\n\t.reg .pred P1;\n\tWL_%=:\n\t"                           \
            "mbarrier.try_wait.parity.acquire.cta.shared::cta.b64 P1, [%0], %1, 0x989680;\n\t" \
            "@P1 bra.uni WD_%=;\n\tbra.uni WL_%=;\n\tWD_%=:\n\t}"                  \
            :: "r"(_m), "r"(_p) : "memory");                                       \
    }                                                                              \
} while (0)

#define TCGEN05_LD_X32(regs, addr) \
    asm volatile("tcgen05.ld.sync.aligned.32x32b.x32.b32 " \
        "{%0, %1, %2, %3, %4, %5, %6, %7, %8, %9, %10, %11, %12, %13, %14, %15, " \
        " %16, %17, %18, %19, %20, %21, %22, %23, %24, %25, %26, %27, %28, %29, %30, %31}, [%32];" \
        : "=r"((regs)[0]),  "=r"((regs)[1]),  "=r"((regs)[2]),  "=r"((regs)[3]), \
          "=r"((regs)[4]),  "=r"((regs)[5]),  "=r"((regs)[6]),  "=r"((regs)[7]), \
          "=r"((regs)[8]),  "=r"((regs)[9]),  "=r"((regs)[10]), "=r"((regs)[11]), \
          "=r"((regs)[12]), "=r"((regs)[13]), "=r"((regs)[14]), "=r"((regs)[15]), \
          "=r"((regs)[16]), "=r"((regs)[17]), "=r"((regs)[18]), "=r"((regs)[19]), \
          "=r"((regs)[20]), "=r"((regs)[21]), "=r"((regs)[22]), "=r"((regs)[23]), \
          "=r"((regs)[24]), "=r"((regs)[25]), "=r"((regs)[26]), "=r"((regs)[27]), \
          "=r"((regs)[28]), "=r"((regs)[29]), "=r"((regs)[30]), "=r"((regs)[31]) \
        : "r"(addr))

// idesc: dtype F32 (1<<4), a/b BF16 (1<<7|1<<10), N=128 (16<<17), M=128 (8<<24)
#define MMA_IDESC 0x8200490u

#define SC_A0 0
#define SC_A1 (16 * 1024)
#define SC_B0 (32 * 1024)
#define SC_B1 (96 * 1024)
#define SC_CTRL (160 * 1024)       // +0 tmem ptr, +8 mbar0, +16 mbar1
#define SC_SMEM (160 * 1024 + 64)

#ifdef HAS_TCGEN05
// issue the 16 MMAs for one 64-K chunk (warp0 elect thread only)
__device__ __forceinline__ void issue_chunk_mmas(uint32_t tmem, uint32_t sb,
                                                 int aoff, int boff, bool first_chunk) {
    unsigned long long ad = MAKE_SMEM_DESC(sb + aoff);
    #pragma unroll
    for (int nt = 0; nt < 4; nt++) {
        unsigned long long bd = MAKE_SMEM_DESC(sb + boff + nt * 16384);
        #pragma unroll
        for (int ks = 0; ks < 4; ks++) {
            uint32_t en = (!first_chunk || ks != 0) ? 1u : 0u;
            asm volatile("{\n\t.reg .pred p;\n\tsetp.ne.u32 p, %4, 0;\n\t"
                "tcgen05.mma.cta_group::1.kind::f16 [%0], %1, %2, %3, {%5, %5, %5, %5}, p;\n\t}"
                :: "r"(tmem + nt * 128), "l"(ad + ks * 2), "l"(bd + ks * 2),
                   "r"(MMA_IDESC), "r"(en), "r"(0u) : "memory");
        }
    }
}
#endif

// ========== kernel: tensor-core projection + fused split (pipelined) ==========
__global__ __launch_bounds__(256) void proj_mma() {
#ifdef HAS_TCGEN05
    extern __shared__ char smem[];
    const uint32_t sb = smem_to_u32(smem);
    const int tid = threadIdx.x;
    const int wid = tid >> 5;
    const int row0 = blockIdx.x * 128;

    if (wid == 0)
        asm volatile("tcgen05.alloc.cta_group::1.sync.aligned.shared::cta.b32 [%0], %1;"
                     :: "r"(sb + SC_CTRL), "r"(512u) : "memory");
    __syncthreads();
    uint32_t tmem;
    asm volatile("ld.shared.b32 %0, [%1];" : "=r"(tmem) : "r"(sb + SC_CTRL));
    if (tid == 0) {
        MBARRIER_INIT(sb + SC_CTRL + 8, 1);
        MBARRIER_INIT(sb + SC_CTRL + 16, 1);
    }
    __syncthreads();

    const int a_idx[6] = { 0, 0, 1, 0, 1, 2 };
    const int b_idx[6] = { 0, 1, 0, 2, 1, 0 };

    auto fill = [&](int buf, int kc) {
        const int t = kc >> 4, koff = (kc & 15) * 64;
        const __nv_bfloat16* Asrc = g_xs  + (size_t)a_idx[t] * M_ROWS * D_DIM;
        const __nv_bfloat16* Bsrc = g_rps + (size_t)b_idx[t] * E_DIM  * D_DIM;
        const int aoff = buf ? SC_A1 : SC_A0;
        const int boff = buf ? SC_B1 : SC_B0;
        #pragma unroll
        for (int r = 0; r < 4; r++) {
            int ci = tid + 256 * r, m = ci >> 3, c8 = ci & 7;
            cp16(sb + aoff + SMEM_SWIZZLE_128B(m * 128 + c8 * 16),
                 Asrc + (size_t)(row0 + m) * D_DIM + koff + c8 * 8);
        }
        #pragma unroll
        for (int r = 0; r < 16; r++) {
            int ci = tid + 256 * r, n = ci >> 3, c8 = ci & 7;
            cp16(sb + boff + SMEM_SWIZZLE_128B(n * 128 + c8 * 16),
                 Bsrc + (size_t)n * D_DIM + koff + c8 * 8);
        }
    };

    int ph[2] = { 0, 0 }, pend[2] = { 0, 0 };
    fill(0, 0); CP_COMMIT();

    for (int kc = 0; kc < 96; kc++) {
        const int buf = kc & 1;
        if (kc + 1 < 96) {
            const int nb = buf ^ 1;
            if (pend[nb]) {
                MBARRIER_WAIT_PARITY(sb + SC_CTRL + 8 + 8 * nb, ph[nb]);
                ph[nb] ^= 1; pend[nb] = 0;
            }
            fill(nb, kc + 1); CP_COMMIT();
            CP_WAIT_1();
        } else {
            CP_WAIT_0();
        }
        asm volatile("fence.proxy.async.shared::cta;" ::: "memory");
        __syncthreads();
        if (wid == 0 && elect_one_pred()) {
            issue_chunk_mmas(tmem, sb, buf ? SC_A1 : SC_A0, buf ? SC_B1 : SC_B0, kc == 0);
            asm volatile("tcgen05.commit.cta_group::1.mbarrier::arrive::one.shared::cluster.b64 [%0];"
                         :: "r"(sb + SC_CTRL + 8 + 8 * buf) : "memory");
        }
        pend[buf] = 1;
    }
    #pragma unroll
    for (int b = 0; b < 2; b++)
        if (pend[b]) {
            MBARRIER_WAIT_PARITY(sb + SC_CTRL + 8 + 8 * b, ph[b]);
            ph[b] ^= 1; pend[b] = 0;
        }
    asm volatile("tcgen05.fence::after_thread_sync;" ::: "memory");

    if (tid < 128) {   // warps 0-3, lane -> row (row = row0 + tid)
        const size_t rbase = (size_t)(row0 + tid) * E_DIM;
        #pragma unroll
        for (int nt = 0; nt < 4; nt++) {
            #pragma unroll
            for (int b4 = 0; b4 < 4; b4++) {
                uint32_t regs[32];
                TCGEN05_LD_X32(regs, tmem + nt * 128 + b4 * 32);
                asm volatile("tcgen05.wait::ld.sync.aligned;" ::: "memory");
                const int cbase = nt * 128 + b4 * 32;
                #pragma unroll
                for (int c = 0; c < 32; c += 2) {
                    __nv_bfloat16 h0[3], h1[3];
                    split3(__uint_as_float(regs[c]),     h0[0], h0[1], h0[2]);
                    split3(__uint_as_float(regs[c + 1]), h1[0], h1[1], h1[2]);
                    #pragma unroll
                    for (int s = 0; s < 3; s++) {
                        __nv_bfloat16 pr[2] = { h0[s], h1[s] };
                        *(uint32_t*)(g_ps + (size_t)s * M_ROWS * E_DIM + rbase + cbase + c)
                            = *(uint32_t*)pr;
                    }
                }
            }
        }
        asm volatile("tcgen05.fence::before_thread_sync;" ::: "memory");
    }
    __syncthreads();
    if (wid == 0)
        asm volatile("tcgen05.dealloc.cta_group::1.sync.aligned.b32 %0, %1;" :: "r"(tmem), "r"(512u));
#endif
}

// ========== kernel: tensor-core score + argmax (pipelined) ==========
__global__ __launch_bounds__(256) void score_mma(float* __restrict__ out) {
#ifdef HAS_TCGEN05
    extern __shared__ char smem[];
    const uint32_t sb = smem_to_u32(smem);
    const int tid = threadIdx.x;
    const int wid = tid >> 5;
    const int row0 = blockIdx.x * 128;

    if (wid == 0)
        asm volatile("tcgen05.alloc.cta_group::1.sync.aligned.shared::cta.b32 [%0], %1;"
                     :: "r"(sb + SC_CTRL), "r"(512u) : "memory");
    __syncthreads();
    uint32_t tmem;
    asm volatile("ld.shared.b32 %0, [%1];" : "=r"(tmem) : "r"(sb + SC_CTRL));
    if (tid == 0) {
        MBARRIER_INIT(sb + SC_CTRL + 8, 1);
        MBARRIER_INIT(sb + SC_CTRL + 16, 1);
    }
    __syncthreads();

    const int a_idx[6] = { 0, 0, 1, 0, 1, 2 };
    const int b_idx[6] = { 0, 1, 0, 2, 1, 0 };

    auto fill = [&](int buf, int gc) {
        const int kc = gc % 48, g = gc / 48;
        const int t = kc >> 3, koff = (kc & 7) * 64;
        const __nv_bfloat16* Asrc = g_ps  + (size_t)a_idx[t] * M_ROWS * E_DIM;
        const __nv_bfloat16* Bsrc = g_cbs + (size_t)b_idx[t] * C_DIM  * E_DIM;
        const int aoff = buf ? SC_A1 : SC_A0;
        const int boff = buf ? SC_B1 : SC_B0;
        #pragma unroll
        for (int r = 0; r < 4; r++) {
            int ci = tid + 256 * r, m = ci >> 3, c8 = ci & 7;
            cp16(sb + aoff + SMEM_SWIZZLE_128B(m * 128 + c8 * 16),
                 Asrc + (size_t)(row0 + m) * E_DIM + koff + c8 * 8);
        }
        #pragma unroll
        for (int r = 0; r < 16; r++) {
            int ci = tid + 256 * r, n = ci >> 3, c8 = ci & 7;
            cp16(sb + boff + SMEM_SWIZZLE_128B(n * 128 + c8 * 16),
                 Bsrc + (size_t)(g * 512 + n) * E_DIM + koff + c8 * 8);
        }
    };

    float best = -3.402823466e38f;
    int besti = 0;
    int ph[2] = { 0, 0 }, pend[2] = { 0, 0 };

    fill(0, 0); CP_COMMIT();

    for (int gc = 0; gc < 384; gc++) {
        const int buf = gc & 1;
        if (gc + 1 < 384) {
            const int nb = buf ^ 1;
            if (pend[nb]) {
                MBARRIER_WAIT_PARITY(sb + SC_CTRL + 8 + 8 * nb, ph[nb]);
                ph[nb] ^= 1; pend[nb] = 0;
            }
            fill(nb, gc + 1); CP_COMMIT();
            CP_WAIT_1();
        } else {
            CP_WAIT_0();
        }
        asm volatile("fence.proxy.async.shared::cta;" ::: "memory");
        __syncthreads();
        if (wid == 0 && elect_one_pred()) {
            issue_chunk_mmas(tmem, sb, buf ? SC_A1 : SC_A0, buf ? SC_B1 : SC_B0, (gc % 48) == 0);
            asm volatile("tcgen05.commit.cta_group::1.mbarrier::arrive::one.shared::cluster.b64 [%0];"
                         :: "r"(sb + SC_CTRL + 8 + 8 * buf) : "memory");
        }
        pend[buf] = 1;

        if ((gc % 48) == 47) {
            // end of C-group: drain, read D, update argmax (ascending c ->
            // strict > keeps FIRST max, matching jnp.argmax)
            #pragma unroll
            for (int b = 0; b < 2; b++)
                if (pend[b]) {
                    MBARRIER_WAIT_PARITY(sb + SC_CTRL + 8 + 8 * b, ph[b]);
                    ph[b] ^= 1; pend[b] = 0;
                }
            asm volatile("tcgen05.fence::after_thread_sync;" ::: "memory");
            const int g = gc / 48;
            if (tid < 128) {
                #pragma unroll
                for (int nt = 0; nt < 4; nt++) {
                    #pragma unroll
                    for (int b4 = 0; b4 < 4; b4++) {
                        uint32_t regs[32];
                        TCGEN05_LD_X32(regs, tmem + nt * 128 + b4 * 32);
                        asm volatile("tcgen05.wait::ld.sync.aligned;" ::: "memory");
                        const int cbase = g * 512 + nt * 128 + b4 * 32;
                        #pragma unroll
                        for (int c = 0; c < 32; c++) {
                            float s = __uint_as_float(regs[c]);
                            if (s > best) { best = s; besti = cbase + c; }
                        }
                    }
                }
                asm volatile("tcgen05.fence::before_thread_sync;" ::: "memory");
            }
            __syncthreads();
        }
    }

    if (tid < 128) out[row0 + tid] = (float)besti;   // harness reads float32
    __syncthreads();
    if (wid == 0)
        asm volatile("tcgen05.dealloc.cta_group::1.sync.aligned.b32 %0, %1;" :: "r"(tmem), "r"(512u));
#endif
}

extern "C" void kernel_launch(void* const* d_in, const int* in_sizes, int n_in,
                              void* d_out, int out_size) {
    const float* x  = nullptr;
    const float* rp = nullptr;
    const float* cb = nullptr;
    for (int i = 0; i < n_in; i++) {
        if (in_sizes[i] == X_ELEMS)       x  = (const float*)d_in[i];
        else if (in_sizes[i] == RP_ELEMS) rp = (const float*)d_in[i];
        else if (in_sizes[i] == CB_ELEMS) cb = (const float*)d_in[i];
    }
    if (!x || !rp || !cb) {
        x  = (const float*)d_in[0];
        rp = (const float*)d_in[1];
        cb = (const float*)d_in[2];
    }
    float* out = (float*)d_out;  // harness reads output as float32

    cudaFuncSetAttribute(proj_mma,  cudaFuncAttributeMaxDynamicSharedMemorySize, SC_SMEM);
    cudaFuncSetAttribute(score_mma, cudaFuncAttributeMaxDynamicSharedMemorySize, SC_SMEM);

    split_x<<<(M_ROWS * D_DIM) / 1024, 256>>>(x);
    split_rpt<<<dim3(E_DIM / 32, D_DIM / 32), dim3(32, 8)>>>(rp);
    split_cbn<<<C_DIM, 128>>>(cb);
    proj_mma<<<M_ROWS / 128, 256, SC_SMEM>>>();
    score_mma<<<M_ROWS / 128, 256, SC_SMEM>>>(out);
}